// round 14
// baseline (speedup 1.0000x reference)
#include <cuda_runtime.h>

#define BB 4
#define TT 32
#define DD 256
#define NN 1024
#define GROUP 32      // CTAs per batch group
#define COLS 32       // G columns owned per CTA
#define NTHR 512      // threads in main kernel (16 warps)
#define CANARY 0x7fffffffu   // NaN bit pattern; computed p values are never NaN

// ---------------- device scratch ----------------
__device__ float g_xn[BB*TT*NN];        // relu(ln(x@E))
__device__ float g_tn[BB*TT*NN];        // relu(ln(targets@E))
__device__ float g_p[BB*TT*2*NN];       // per-(batch,step,phase) exchange, canary-filled
__device__ float g_reason[BB*TT*NN];    // max(p1,p2,p3)

// ---------------- dataflow primitives (data IS the flag) ----------------
__device__ __forceinline__ void publish2(float* p, float a0, float a1) {
  asm volatile("st.relaxed.gpu.global.v2.f32 [%0], {%1,%2};"
               :: "l"(p), "f"(a0), "f"(a1) : "memory");
}
__device__ __forceinline__ float ldx(const float* p) {
  float v;
  asm volatile("ld.relaxed.gpu.global.f32 %0, [%1];" : "=f"(v) : "l"(p) : "memory");
  return v;
}

// ---------------- kernel 1: neurons = relu(layernorm(X @ E)) ----------------
// 1024 threads, 1 row per block, grid = 128. Canary-fills g_p.
__global__ void __launch_bounds__(1024) prep_kernel(const float* __restrict__ x_seq,
                                                    const float* __restrict__ targets,
                                                    const float* __restrict__ E) {
  __shared__ float xs[DD], ts[DD];
  __shared__ float2 red[32];
  int row = blockIdx.x;            // b*TT + t
  int tid = threadIdx.x;           // column 0..1023
  int w = tid >> 5, l = tid & 31;

  // canary-fill g_p (1 MB): 131072 threads x 1 float2 each
  {
    int gtid = row * 1024 + tid;
    float c = __uint_as_float(CANARY);
    float2 cv; cv.x = c; cv.y = c;
    ((float2*)g_p)[gtid] = cv;
  }

  if (tid < DD) {
    xs[tid] = x_seq[row*DD + tid];
    ts[tid] = targets[row*DD + tid];
  }
  __syncthreads();

  float ax = 0.f, at = 0.f;
#pragma unroll 8
  for (int k = 0; k < DD; ++k) {
    float e = __ldg(E + k*NN + tid);
    ax += xs[k]*e;
    at += ts[k]*e;
  }

  {
    float s1 = ax, s2 = ax*ax;
#pragma unroll
    for (int o = 16; o; o >>= 1) {
      s1 += __shfl_xor_sync(0xffffffffu, s1, o);
      s2 += __shfl_xor_sync(0xffffffffu, s2, o);
    }
    if (l == 0) { red[w].x = s1; red[w].y = s2; }
    __syncthreads();
    float t1 = 0.f, t2 = 0.f;
#pragma unroll
    for (int i = 0; i < 32; ++i) { t1 += red[i].x; t2 += red[i].y; }
    float mu  = t1 * (1.0f/NN);
    float inv = rsqrtf(t2*(1.0f/NN) - mu*mu + 1e-5f);
    g_xn[row*NN + tid] = fmaxf(0.f, (ax - mu)*inv);
  }
  __syncthreads();
  {
    float s1 = at, s2 = at*at;
#pragma unroll
    for (int o = 16; o; o >>= 1) {
      s1 += __shfl_xor_sync(0xffffffffu, s1, o);
      s2 += __shfl_xor_sync(0xffffffffu, s2, o);
    }
    if (l == 0) { red[w].x = s1; red[w].y = s2; }
    __syncthreads();
    float t1 = 0.f, t2 = 0.f;
#pragma unroll
    for (int i = 0; i < 32; ++i) { t1 += red[i].x; t2 += red[i].y; }
    float mu  = t1 * (1.0f/NN);
    float inv = rsqrtf(t2*(1.0f/NN) - mu*mu + 1e-5f);
    g_tn[row*NN + tid] = fmaxf(0.f, (at - mu)*inv);
  }
}

// ---------------- streaming consume: warp reads 32 chunks from L2, pipelined
// acc += p[l + 32*j] * gr[j]; canary-retry per chunk; depth-8 prefetch.
#define CONSUME(P, l, gr0, gr1, a0, a1)                                        \
  {                                                                            \
    float pv[8];                                                               \
    _Pragma("unroll")                                                          \
    for (int i = 0; i < 8; ++i) pv[i] = ldx((P) + (i << 5) + (l));             \
    _Pragma("unroll")                                                          \
    for (int j = 0; j < 32; ++j) {                                             \
      float v = pv[j & 7];                                                     \
      while (__any_sync(0xffffffffu, __float_as_uint(v) == CANARY))            \
        v = ldx((P) + (j << 5) + (l));                                         \
      if (j + 8 < 32) pv[j & 7] = ldx((P) + ((j + 8) << 5) + (l));             \
      a0 += v * gr0[j];                                                        \
      a1 += v * gr1[j];                                                        \
    }                                                                          \
  }

// ---------------- kernel 2: persistent scan, warp-level dataflow -----------
// CTA (b, part) owns G[:, part*32 .. +31]. 16 warps x 2 cols each.
// NO block-wide syncs in the step loop: p buffers are per-(t,phase), write-once.
__global__ void __launch_bounds__(NTHR, 1) main_kernel() {
  extern __shared__ float sm[];
  float* xall = sm;                 // TT*NN = 32768 floats (128 KB)
  float* tba  = xall + TT*NN;       // TT*COLS 0.5*tn values

  int cta  = blockIdx.x;
  int b    = cta >> 5;
  int part = cta & 31;
  int mbase = part * COLS;
  int tid = threadIdx.x, w = tid >> 5, l = tid & 31;
  int cbase = mbase + w*2;

  float gr0[32], gr1[32];
#pragma unroll
  for (int j = 0; j < 32; ++j) {
    int n = l + 32*j;
    gr0[j] = (n == cbase)     ? 0.01f : 0.0f;
    gr1[j] = (n == cbase + 1) ? 0.01f : 0.0f;
  }

  // one-time preload: all steps' x-neurons + this CTA's tn slice
  {
    const float4* src = (const float4*)(g_xn + b*TT*NN);
    float4* dst = (float4*)xall;
    for (int i = tid; i < TT*NN/4; i += NTHR) dst[i] = src[i];
    for (int i = tid; i < TT*COLS; i += NTHR) {
      int t = i >> 5, c = i & 31;
      tba[i] = 0.5f * g_tn[(b*TT + t)*NN + mbase + c];
    }
  }
  __syncthreads();   // the ONLY block-wide sync

  for (int t = 0; t < TT; ++t) {
    const float* xc = xall + t*NN;
    const float* xp = xall + (t-1)*NN;   // valid when t>0
    float tv0 = tba[t*COLS + w*2 + 0];
    float tv1 = tba[t*COLS + w*2 + 1];
    float* pbase = g_p + (b*TT + t)*2*NN;  // [phase][NN]

    float acc0 = 0.f, acc1 = 0.f;
    float r0, r1;

    // ---- phase 1: apply pending rank-1 max-update (t>0), compute p1 ----
    if (t > 0) {
#pragma unroll
      for (int j = 0; j < 32; ++j) {
        float xpv = xp[l + 32*j];
        float xcv = xc[l + 32*j];
        gr0[j] = fmaxf(gr0[j], xpv*tv0);
        gr1[j] = fmaxf(gr1[j], xpv*tv1);
        acc0 += xcv*gr0[j];
        acc1 += xcv*gr1[j];
      }
    } else {
#pragma unroll
      for (int j = 0; j < 32; ++j) {
        float xcv = xc[l + 32*j];
        acc0 += xcv*gr0[j];
        acc1 += xcv*gr1[j];
      }
    }
#pragma unroll
    for (int o = 16; o; o >>= 1) {
      acc0 += __shfl_xor_sync(0xffffffffu, acc0, o);
      acc1 += __shfl_xor_sync(0xffffffffu, acc1, o);
    }
    if (l == 0) publish2(pbase + cbase, acc0, acc1);
    r0 = acc0; r1 = acc1;

    // ---- phase 2: p2 = p1 . G  (streaming consume from L2) ----
    acc0 = 0.f; acc1 = 0.f;
    CONSUME(pbase, l, gr0, gr1, acc0, acc1);
#pragma unroll
    for (int o = 16; o; o >>= 1) {
      acc0 += __shfl_xor_sync(0xffffffffu, acc0, o);
      acc1 += __shfl_xor_sync(0xffffffffu, acc1, o);
    }
    if (l == 0) publish2(pbase + NN + cbase, acc0, acc1);
    r0 = fmaxf(r0, acc0); r1 = fmaxf(r1, acc1);

    // ---- phase 3: p3 = p2 . G  (streaming consume) ----
    acc0 = 0.f; acc1 = 0.f;
    CONSUME(pbase + NN, l, gr0, gr1, acc0, acc1);
#pragma unroll
    for (int o = 16; o; o >>= 1) {
      acc0 += __shfl_xor_sync(0xffffffffu, acc0, o);
      acc1 += __shfl_xor_sync(0xffffffffu, acc1, o);
    }
    r0 = fmaxf(r0, acc0); r1 = fmaxf(r1, acc1);

    if (l == 0) {
      float2 st; st.x = r0; st.y = r1;
      *(float2*)(&g_reason[(b*TT + t)*NN + cbase]) = st;
    }
  }
}

// ---------------- kernel 3: y = relu(reasoning @ Dy) ----------------
__global__ void __launch_bounds__(256) out_kernel(const float* __restrict__ Dy,
                                                  float* __restrict__ out) {
  __shared__ float rs[4*NN];
  int rbase = blockIdx.x * 4;      // grid 32 -> 128 rows
  int tid = threadIdx.x;
  int c4 = tid & 63;               // float4 column group
  int r  = tid >> 6;               // row within block (0..3)
  for (int i = tid; i < 4*NN; i += 256) rs[i] = g_reason[rbase*NN + i];
  __syncthreads();

  const float4* Dy4 = (const float4*)Dy;  // [1024][64] float4
  const float* rr = rs + r*NN;
  float4 a = make_float4(0.f,0.f,0.f,0.f);
#pragma unroll 8
  for (int n = 0; n < NN; ++n) {
    float4 d = Dy4[n*64 + c4];
    float pv = rr[n];
    a.x += pv*d.x; a.y += pv*d.y; a.z += pv*d.z; a.w += pv*d.w;
  }
  float4 o;
  o.x = fmaxf(a.x,0.f); o.y = fmaxf(a.y,0.f);
  o.z = fmaxf(a.z,0.f); o.w = fmaxf(a.w,0.f);
  ((float4*)(out + (rbase + r)*DD))[c4] = o;
}

// ---------------- launch ----------------
extern "C" void kernel_launch(void* const* d_in, const int* in_sizes, int n_in,
                              void* d_out, int out_size) {
  const float* x_seq   = (const float*)d_in[0];  // [4,32,256]
  const float* targets = (const float*)d_in[1];  // [4,32,256]
  const float* E       = (const float*)d_in[2];  // [256,1024]
  const float* Dy      = (const float*)d_in[3];  // [1024,256]
  float* out = (float*)d_out;                    // [4,32,256]

  int smem = (TT*NN + TT*COLS) * (int)sizeof(float);  // ~132 KB
  static int smem_set = 0;
  if (!smem_set) {
    cudaFuncSetAttribute(main_kernel, cudaFuncAttributeMaxDynamicSharedMemorySize, smem);
    smem_set = 1;
  }

  prep_kernel<<<BB*TT, 1024>>>(x_seq, targets, E);   // also canary-fills g_p
  main_kernel<<<BB*GROUP, NTHR, smem>>>();
  out_kernel<<<32, 256>>>(Dy, out);
}

// round 15
// speedup vs baseline: 2.9254x; 2.9254x over previous
#include <cuda_runtime.h>

#define BB 4
#define TT 32
#define DD 256
#define NN 1024
#define GROUP 32      // CTAs per batch group
#define COLS 32       // G columns owned per CTA
#define NTHR 512      // threads in main kernel (16 warps)
#define CANARY 0x7fffffffu   // NaN bit pattern; computed p values are never NaN

// ---------------- device scratch ----------------
__device__ float g_xn[BB*TT*NN];     // relu(ln(x@E))
__device__ float g_tn[BB*TT*NN];     // relu(ln(targets@E))
__device__ float g_p1[BB*TT*NN];     // p1 per (batch,step), canary-filled
__device__ float g_p2[BB*TT*NN];     // p2 per (batch,step), canary-filled
__device__ float g_reason[BB*TT*NN]; // max(p1,p2,p3)

// ---------------- dataflow primitives (data IS the flag) ----------------
__device__ __forceinline__ void publish2(float* p, float a0, float a1) {
  asm volatile("st.relaxed.gpu.global.v2.f32 [%0], {%1,%2};"
               :: "l"(p), "f"(a0), "f"(a1) : "memory");
}
__device__ __forceinline__ float2 poll2(const float* p) {
  float2 v;
  asm volatile("ld.relaxed.gpu.global.v2.f32 {%0,%1}, [%2];"
               : "=f"(v.x), "=f"(v.y) : "l"(p) : "memory");
  while (__float_as_uint(v.x) == CANARY) {
    asm volatile("ld.relaxed.gpu.global.v2.f32 {%0,%1}, [%2];"
                 : "=f"(v.x), "=f"(v.y) : "l"(p) : "memory");
  }
  return v;
}

// ---------------- kernel 1: neurons = relu(layernorm(X @ E)) ----------------
// 1024 threads, 1 row per block, grid = 128. Canary-fills g_p1/g_p2.
__global__ void __launch_bounds__(1024) prep_kernel(const float* __restrict__ x_seq,
                                                    const float* __restrict__ targets,
                                                    const float* __restrict__ E) {
  __shared__ float xs[DD], ts[DD];
  __shared__ float2 red[32];
  int row = blockIdx.x;            // b*TT + t
  int tid = threadIdx.x;           // column 0..1023
  int w = tid >> 5, l = tid & 31;

  // canary-fill g_p1 + g_p2 (1 MB total = 131072 float2s = 128 blk x 1024 thr)
  {
    int gtid = row * 1024 + tid;
    float c = __uint_as_float(CANARY);
    float2 cv; cv.x = c; cv.y = c;
    if (gtid < BB*TT*NN/2) ((float2*)g_p1)[gtid] = cv;
    else                   ((float2*)g_p2)[gtid - BB*TT*NN/2] = cv;
  }

  if (tid < DD) {
    xs[tid] = x_seq[row*DD + tid];
    ts[tid] = targets[row*DD + tid];
  }
  __syncthreads();

  float ax = 0.f, at = 0.f;
#pragma unroll 8
  for (int k = 0; k < DD; ++k) {
    float e = __ldg(E + k*NN + tid);
    ax += xs[k]*e;
    at += ts[k]*e;
  }

  {
    float s1 = ax, s2 = ax*ax;
#pragma unroll
    for (int o = 16; o; o >>= 1) {
      s1 += __shfl_xor_sync(0xffffffffu, s1, o);
      s2 += __shfl_xor_sync(0xffffffffu, s2, o);
    }
    if (l == 0) { red[w].x = s1; red[w].y = s2; }
    __syncthreads();
    float t1 = 0.f, t2 = 0.f;
#pragma unroll
    for (int i = 0; i < 32; ++i) { t1 += red[i].x; t2 += red[i].y; }
    float mu  = t1 * (1.0f/NN);
    float inv = rsqrtf(t2*(1.0f/NN) - mu*mu + 1e-5f);
    g_xn[row*NN + tid] = fmaxf(0.f, (ax - mu)*inv);
  }
  __syncthreads();
  {
    float s1 = at, s2 = at*at;
#pragma unroll
    for (int o = 16; o; o >>= 1) {
      s1 += __shfl_xor_sync(0xffffffffu, s1, o);
      s2 += __shfl_xor_sync(0xffffffffu, s2, o);
    }
    if (l == 0) { red[w].x = s1; red[w].y = s2; }
    __syncthreads();
    float t1 = 0.f, t2 = 0.f;
#pragma unroll
    for (int i = 0; i < 32; ++i) { t1 += red[i].x; t2 += red[i].y; }
    float mu  = t1 * (1.0f/NN);
    float inv = rsqrtf(t2*(1.0f/NN) - mu*mu + 1e-5f);
    g_tn[row*NN + tid] = fmaxf(0.f, (at - mu)*inv);
  }
}

// ---------------- kernel 2: persistent scan, 3-pass (G is input-determined) --
// CTA (b, part) owns G[:, part*32 .. +31]. 16 warps x 2 cols each.
// Thread (w, l): cols cbase = part*32 + w*2 + {0,1}, rows n = l + 32*j.
__global__ void __launch_bounds__(NTHR, 1) main_kernel() {
  extern __shared__ float sm[];
  float* xall = sm;                 // TT*NN x-neurons (128 KB)
  float* tba  = xall + TT*NN;       // TT*COLS 0.5*tn values
  float* pb   = tba + TT*COLS;      // NN staged p vector
  float* rm   = pb + NN;            // TT*COLS running max(p1,p2) per col

  int cta  = blockIdx.x;
  int b    = cta >> 5;
  int part = cta & 31;
  int mbase = part * COLS;
  int tid = threadIdx.x, w = tid >> 5, l = tid & 31;
  int cbase = mbase + w*2;

  // one-time preload
  {
    const float4* src = (const float4*)(g_xn + b*TT*NN);
    float4* dst = (float4*)xall;
    for (int i = tid; i < TT*NN/4; i += NTHR) dst[i] = src[i];
    for (int i = tid; i < TT*COLS; i += NTHR) {
      int t = i >> 5, c = i & 31;
      tba[i] = 0.5f * g_tn[(b*TT + t)*NN + mbase + c];
    }
  }
  __syncthreads();

  float gr0[32], gr1[32];

#define INIT_G()                                                 \
  _Pragma("unroll")                                              \
  for (int j = 0; j < 32; ++j) {                                 \
    int n = l + 32*j;                                            \
    gr0[j] = (n == cbase)     ? 0.01f : 0.0f;                    \
    gr1[j] = (n == cbase + 1) ? 0.01f : 0.0f;                    \
  }

#define UPDATE_G(t)                                              \
  if ((t) > 0) {                                                 \
    const float* xp_ = xall + ((t)-1)*NN;                        \
    float tv0_ = tba[(t)*COLS + w*2 + 0];                        \
    float tv1_ = tba[(t)*COLS + w*2 + 1];                        \
    _Pragma("unroll")                                            \
    for (int j = 0; j < 32; ++j) {                               \
      float xpv = xp_[l + 32*j];                                 \
      gr0[j] = fmaxf(gr0[j], xpv*tv0_);                          \
      gr1[j] = fmaxf(gr1[j], xpv*tv1_);                          \
    }                                                            \
  }

#define DOT_REDUCE(vec, a0, a1)                                  \
  a0 = 0.f; a1 = 0.f;                                            \
  _Pragma("unroll")                                              \
  for (int j = 0; j < 32; ++j) {                                 \
    float pv = (vec)[l + 32*j];                                  \
    a0 += pv*gr0[j];                                             \
    a1 += pv*gr1[j];                                             \
  }                                                              \
  _Pragma("unroll")                                              \
  for (int o = 16; o; o >>= 1) {                                 \
    a0 += __shfl_xor_sync(0xffffffffu, a0, o);                   \
    a1 += __shfl_xor_sync(0xffffffffu, a1, o);                   \
  }

  // ================= pass 1: publish all p1(t), no waiting =================
  INIT_G();
  for (int t = 0; t < TT; ++t) {
    UPDATE_G(t);
    const float* xc = xall + t*NN;
    float acc0, acc1;
    DOT_REDUCE(xc, acc0, acc1);
    if (l == 0) publish2(g_p1 + (b*TT + t)*NN + cbase, acc0, acc1);
  }

  // ================= pass 2: p2(t) = p1(t) . G_t =================
  INIT_G();
  for (int t = 0; t < TT; ++t) {
    UPDATE_G(t);
    // stage p1(t): mostly no wait (published in everyone's pass 1)
    {
      float2 v = poll2(g_p1 + (b*TT + t)*NN + 2*tid);
      ((float2*)pb)[tid] = v;
    }
    __syncthreads();
    float acc0, acc1;
    DOT_REDUCE(pb, acc0, acc1);
    if (l == 0) {
      publish2(g_p2 + (b*TT + t)*NN + cbase, acc0, acc1);
      rm[t*COLS + w*2 + 0] = fmaxf(pb[cbase],     acc0);
      rm[t*COLS + w*2 + 1] = fmaxf(pb[cbase + 1], acc1);
    }
    __syncthreads();   // pb reuse next step
  }

  // ================= pass 3: p3(t) = p2(t) . G_t, write result =============
  INIT_G();
  for (int t = 0; t < TT; ++t) {
    UPDATE_G(t);
    {
      float2 v = poll2(g_p2 + (b*TT + t)*NN + 2*tid);
      ((float2*)pb)[tid] = v;
    }
    __syncthreads();
    float acc0, acc1;
    DOT_REDUCE(pb, acc0, acc1);
    if (l == 0) {
      float2 st;
      st.x = fmaxf(rm[t*COLS + w*2 + 0], acc0);
      st.y = fmaxf(rm[t*COLS + w*2 + 1], acc1);
      *(float2*)(&g_reason[(b*TT + t)*NN + cbase]) = st;
    }
    __syncthreads();
  }
}

// ---------------- kernel 3: y = relu(reasoning @ Dy) ----------------
__global__ void __launch_bounds__(256) out_kernel(const float* __restrict__ Dy,
                                                  float* __restrict__ out) {
  __shared__ float rs[4*NN];
  int rbase = blockIdx.x * 4;      // grid 32 -> 128 rows
  int tid = threadIdx.x;
  int c4 = tid & 63;               // float4 column group
  int r  = tid >> 6;               // row within block (0..3)
  for (int i = tid; i < 4*NN; i += 256) rs[i] = g_reason[rbase*NN + i];
  __syncthreads();

  const float4* Dy4 = (const float4*)Dy;  // [1024][64] float4
  const float* rr = rs + r*NN;
  float4 a = make_float4(0.f,0.f,0.f,0.f);
#pragma unroll 8
  for (int n = 0; n < NN; ++n) {
    float4 d = Dy4[n*64 + c4];
    float pv = rr[n];
    a.x += pv*d.x; a.y += pv*d.y; a.z += pv*d.z; a.w += pv*d.w;
  }
  float4 o;
  o.x = fmaxf(a.x,0.f); o.y = fmaxf(a.y,0.f);
  o.z = fmaxf(a.z,0.f); o.w = fmaxf(a.w,0.f);
  ((float4*)(out + (rbase + r)*DD))[c4] = o;
}

// ---------------- launch ----------------
extern "C" void kernel_launch(void* const* d_in, const int* in_sizes, int n_in,
                              void* d_out, int out_size) {
  const float* x_seq   = (const float*)d_in[0];  // [4,32,256]
  const float* targets = (const float*)d_in[1];  // [4,32,256]
  const float* E       = (const float*)d_in[2];  // [256,1024]
  const float* Dy      = (const float*)d_in[3];  // [1024,256]
  float* out = (float*)d_out;                    // [4,32,256]

  int smem = (TT*NN + TT*COLS + NN + TT*COLS) * (int)sizeof(float);  // ~144 KB
  static int smem_set = 0;
  if (!smem_set) {
    cudaFuncSetAttribute(main_kernel, cudaFuncAttributeMaxDynamicSharedMemorySize, smem);
    smem_set = 1;
  }

  prep_kernel<<<BB*TT, 1024>>>(x_seq, targets, E);   // also canary-fills g_p1/g_p2
  main_kernel<<<BB*GROUP, NTHR, smem>>>();
  out_kernel<<<32, 256>>>(Dy, out);
}

// round 16
// speedup vs baseline: 3.1551x; 1.0785x over previous
#include <cuda_runtime.h>

#define BB 4
#define TT 32
#define DD 256
#define NN 1024
#define GROUP 32      // CTAs per batch group
#define COLS 32       // G columns owned per CTA
#define NTHR 512      // threads in main kernel (16 warps)
#define CANARY 0x7fffffffu   // NaN bit pattern; computed p values are never NaN

// ---------------- device scratch ----------------
__device__ float g_xn[BB*TT*NN];     // relu(ln(x@E))
__device__ float g_tn[BB*TT*NN];     // relu(ln(targets@E))
__device__ float g_p1[BB*TT*NN];     // p1 per (batch,step), canary-filled
__device__ float g_p2[BB*TT*NN];     // p2 per (batch,step), canary-filled
__device__ float g_reason[BB*TT*NN]; // max(p1,p2,p3)

// ---------------- dataflow primitives (data IS the flag) ----------------
__device__ __forceinline__ void publish2(float* p, float a0, float a1) {
  asm volatile("st.relaxed.gpu.global.v2.f32 [%0], {%1,%2};"
               :: "l"(p), "f"(a0), "f"(a1) : "memory");
}
__device__ __forceinline__ float2 poll2(const float* p) {
  float2 v;
  asm volatile("ld.relaxed.gpu.global.v2.f32 {%0,%1}, [%2];"
               : "=f"(v.x), "=f"(v.y) : "l"(p) : "memory");
  while (__float_as_uint(v.x) == CANARY) {
    asm volatile("ld.relaxed.gpu.global.v2.f32 {%0,%1}, [%2];"
                 : "=f"(v.x), "=f"(v.y) : "l"(p) : "memory");
  }
  return v;
}

// ---------------- kernel 1: neurons = relu(layernorm(X @ E)) ----------------
// 512 threads, 2 cols each (float2), explicit depth-8 LDG double buffering.
__global__ void __launch_bounds__(512) prep_kernel(const float* __restrict__ x_seq,
                                                   const float* __restrict__ targets,
                                                   const float* __restrict__ E) {
  __shared__ float xs[DD], ts[DD];
  __shared__ float2 red[16];
  int row = blockIdx.x;            // b*TT + t
  int tid = threadIdx.x;           // 0..511 -> cols {2tid, 2tid+1}
  int w = tid >> 5, l = tid & 31;

  // canary-fill g_p1 + g_p2: 128 blk x 512 thr x 2 float2 = 131072 float2s
  {
    int gtid = row * 512 + tid;    // 0..65535
    float c = __uint_as_float(CANARY);
    float2 cv; cv.x = c; cv.y = c;
    ((float2*)g_p1)[gtid] = cv;
    ((float2*)g_p2)[gtid] = cv;
  }

  if (tid < DD) {
    xs[tid] = x_seq[row*DD + tid];
    ts[tid] = targets[row*DD + tid];
  }
  __syncthreads();

  const float2* E2 = (const float2*)E;   // [256][512]
  float2 ax = make_float2(0.f, 0.f), at = make_float2(0.f, 0.f);
  float2 buf[8];
#pragma unroll
  for (int i = 0; i < 8; ++i) buf[i] = __ldg(E2 + i*512 + tid);

  for (int k0 = 0; k0 < DD; k0 += 8) {
    float2 cur[8];
#pragma unroll
    for (int i = 0; i < 8; ++i) cur[i] = buf[i];
    if (k0 + 8 < DD) {
#pragma unroll
      for (int i = 0; i < 8; ++i) buf[i] = __ldg(E2 + (k0 + 8 + i)*512 + tid);
    }
#pragma unroll
    for (int i = 0; i < 8; ++i) {
      float xv = xs[k0 + i], tv = ts[k0 + i];
      ax.x += xv*cur[i].x; ax.y += xv*cur[i].y;
      at.x += tv*cur[i].x; at.y += tv*cur[i].y;
    }
  }

  {
    float s1 = ax.x + ax.y, s2 = ax.x*ax.x + ax.y*ax.y;
#pragma unroll
    for (int o = 16; o; o >>= 1) {
      s1 += __shfl_xor_sync(0xffffffffu, s1, o);
      s2 += __shfl_xor_sync(0xffffffffu, s2, o);
    }
    if (l == 0) { red[w].x = s1; red[w].y = s2; }
    __syncthreads();
    float t1 = 0.f, t2 = 0.f;
#pragma unroll
    for (int i = 0; i < 16; ++i) { t1 += red[i].x; t2 += red[i].y; }
    float mu  = t1 * (1.0f/NN);
    float inv = rsqrtf(t2*(1.0f/NN) - mu*mu + 1e-5f);
    float2 o2;
    o2.x = fmaxf(0.f, (ax.x - mu)*inv);
    o2.y = fmaxf(0.f, (ax.y - mu)*inv);
    ((float2*)(g_xn + row*NN))[tid] = o2;
  }
  __syncthreads();
  {
    float s1 = at.x + at.y, s2 = at.x*at.x + at.y*at.y;
#pragma unroll
    for (int o = 16; o; o >>= 1) {
      s1 += __shfl_xor_sync(0xffffffffu, s1, o);
      s2 += __shfl_xor_sync(0xffffffffu, s2, o);
    }
    if (l == 0) { red[w].x = s1; red[w].y = s2; }
    __syncthreads();
    float t1 = 0.f, t2 = 0.f;
#pragma unroll
    for (int i = 0; i < 16; ++i) { t1 += red[i].x; t2 += red[i].y; }
    float mu  = t1 * (1.0f/NN);
    float inv = rsqrtf(t2*(1.0f/NN) - mu*mu + 1e-5f);
    float2 o2;
    o2.x = fmaxf(0.f, (at.x - mu)*inv);
    o2.y = fmaxf(0.f, (at.y - mu)*inv);
    ((float2*)(g_tn + row*NN))[tid] = o2;
  }
}

// ---------------- kernel 2: persistent scan, 2-pass with one-step lag --------
// Pass A: step t consumes p1(t-1) -> p2(t-1) with G_{t-1}, then update+p1(t).
// Pass B: trailing p3 pass (consume p2(t), fused update+dot).
__global__ void __launch_bounds__(NTHR, 1) main_kernel() {
  extern __shared__ float sm[];
  float* xall = sm;                 // TT*NN x-neurons (128 KB)
  float* tba  = xall + TT*NN;       // TT*COLS 0.5*tn values
  float* pb   = tba + TT*COLS;      // NN staged p vector
  float* rm   = pb + NN;            // TT*COLS running max(p1,p2) per col

  int cta  = blockIdx.x;
  int b    = cta >> 5;
  int part = cta & 31;
  int mbase = part * COLS;
  int tid = threadIdx.x, w = tid >> 5, l = tid & 31;
  int cbase = mbase + w*2;

  // one-time preload
  {
    const float4* src = (const float4*)(g_xn + b*TT*NN);
    float4* dst = (float4*)xall;
    for (int i = tid; i < TT*NN/4; i += NTHR) dst[i] = src[i];
    for (int i = tid; i < TT*COLS; i += NTHR) {
      int t = i >> 5, c = i & 31;
      tba[i] = 0.5f * g_tn[(b*TT + t)*NN + mbase + c];
    }
  }
  __syncthreads();

  float gr0[32], gr1[32];

#define INIT_G()                                                 \
  _Pragma("unroll")                                              \
  for (int j = 0; j < 32; ++j) {                                 \
    int n = l + 32*j;                                            \
    gr0[j] = (n == cbase)     ? 0.01f : 0.0f;                    \
    gr1[j] = (n == cbase + 1) ? 0.01f : 0.0f;                    \
  }

#define WARP_REDUCE(a0, a1)                                      \
  _Pragma("unroll")                                              \
  for (int o = 16; o; o >>= 1) {                                 \
    a0 += __shfl_xor_sync(0xffffffffu, a0, o);                   \
    a1 += __shfl_xor_sync(0xffffffffu, a1, o);                   \
  }

  // ================= pass A: p1 + p2 with one-step lag =================
  INIT_G();
  for (int t = 0; t < TT; ++t) {
    const float* xc = xall + t*NN;
    float acc0, acc1;

    if (t > 0) {
      // ---- consume p1(t-1), compute p2(t-1) with G_{t-1} (pre-update) ----
      {
        float2 v = poll2(g_p1 + (b*TT + t - 1)*NN + 2*tid);
        ((float2*)pb)[tid] = v;
      }
      __syncthreads();
      acc0 = 0.f; acc1 = 0.f;
#pragma unroll
      for (int j = 0; j < 32; ++j) {
        float pv = pb[l + 32*j];
        acc0 += pv*gr0[j];
        acc1 += pv*gr1[j];
      }
      WARP_REDUCE(acc0, acc1);
      if (l == 0) {
        publish2(g_p2 + (b*TT + t - 1)*NN + cbase, acc0, acc1);
        rm[(t-1)*COLS + w*2 + 0] = fmaxf(pb[cbase],     acc0);
        rm[(t-1)*COLS + w*2 + 1] = fmaxf(pb[cbase + 1], acc1);
      }

      // ---- fused: update G -> G_t, compute p1(t) ----
      const float* xp = xall + (t-1)*NN;
      float tv0 = tba[t*COLS + w*2 + 0];
      float tv1 = tba[t*COLS + w*2 + 1];
      acc0 = 0.f; acc1 = 0.f;
#pragma unroll
      for (int j = 0; j < 32; ++j) {
        float xpv = xp[l + 32*j];
        float xcv = xc[l + 32*j];
        gr0[j] = fmaxf(gr0[j], xpv*tv0);
        gr1[j] = fmaxf(gr1[j], xpv*tv1);
        acc0 += xcv*gr0[j];
        acc1 += xcv*gr1[j];
      }
      WARP_REDUCE(acc0, acc1);
      if (l == 0) publish2(g_p1 + (b*TT + t)*NN + cbase, acc0, acc1);
      __syncthreads();   // protect pb before next step's staging
    } else {
      acc0 = 0.f; acc1 = 0.f;
#pragma unroll
      for (int j = 0; j < 32; ++j) {
        float xcv = xc[l + 32*j];
        acc0 += xcv*gr0[j];
        acc1 += xcv*gr1[j];
      }
      WARP_REDUCE(acc0, acc1);
      if (l == 0) publish2(g_p1 + (b*TT)*NN + cbase, acc0, acc1);
    }
  }
  // epilogue: p2(TT-1) with final G_{TT-1}
  {
    float2 v = poll2(g_p1 + (b*TT + TT - 1)*NN + 2*tid);
    ((float2*)pb)[tid] = v;
    __syncthreads();
    float acc0 = 0.f, acc1 = 0.f;
#pragma unroll
    for (int j = 0; j < 32; ++j) {
      float pv = pb[l + 32*j];
      acc0 += pv*gr0[j];
      acc1 += pv*gr1[j];
    }
    WARP_REDUCE(acc0, acc1);
    if (l == 0) {
      publish2(g_p2 + (b*TT + TT - 1)*NN + cbase, acc0, acc1);
      rm[(TT-1)*COLS + w*2 + 0] = fmaxf(pb[cbase],     acc0);
      rm[(TT-1)*COLS + w*2 + 1] = fmaxf(pb[cbase + 1], acc1);
    }
    __syncthreads();
  }

  // ================= pass B: p3(t) = p2(t) . G_t, write result =============
  INIT_G();
  for (int t = 0; t < TT; ++t) {
    // stage p2(t) — published long ago relative to this trailing pass
    {
      float2 v = poll2(g_p2 + (b*TT + t)*NN + 2*tid);
      ((float2*)pb)[tid] = v;
    }
    __syncthreads();
    float acc0 = 0.f, acc1 = 0.f;
    if (t > 0) {
      const float* xp = xall + (t-1)*NN;
      float tv0 = tba[t*COLS + w*2 + 0];
      float tv1 = tba[t*COLS + w*2 + 1];
#pragma unroll
      for (int j = 0; j < 32; ++j) {
        float xpv = xp[l + 32*j];
        float pv  = pb[l + 32*j];
        gr0[j] = fmaxf(gr0[j], xpv*tv0);
        gr1[j] = fmaxf(gr1[j], xpv*tv1);
        acc0 += pv*gr0[j];
        acc1 += pv*gr1[j];
      }
    } else {
#pragma unroll
      for (int j = 0; j < 32; ++j) {
        float pv = pb[l + 32*j];
        acc0 += pv*gr0[j];
        acc1 += pv*gr1[j];
      }
    }
    WARP_REDUCE(acc0, acc1);
    if (l == 0) {
      float2 st;
      st.x = fmaxf(rm[t*COLS + w*2 + 0], acc0);
      st.y = fmaxf(rm[t*COLS + w*2 + 1], acc1);
      *(float2*)(&g_reason[(b*TT + t)*NN + cbase]) = st;
    }
    __syncthreads();
  }
}

// ---------------- kernel 3: y = relu(reasoning @ Dy) ----------------
__global__ void __launch_bounds__(256) out_kernel(const float* __restrict__ Dy,
                                                  float* __restrict__ out) {
  __shared__ float rs[4*NN];
  int rbase = blockIdx.x * 4;      // grid 32 -> 128 rows
  int tid = threadIdx.x;
  int c4 = tid & 63;               // float4 column group
  int r  = tid >> 6;               // row within block (0..3)
  for (int i = tid; i < 4*NN; i += 256) rs[i] = g_reason[rbase*NN + i];
  __syncthreads();

  const float4* Dy4 = (const float4*)Dy;  // [1024][64] float4
  const float* rr = rs + r*NN;
  float4 a = make_float4(0.f,0.f,0.f,0.f);
#pragma unroll 8
  for (int n = 0; n < NN; ++n) {
    float4 d = Dy4[n*64 + c4];
    float pv = rr[n];
    a.x += pv*d.x; a.y += pv*d.y; a.z += pv*d.z; a.w += pv*d.w;
  }
  float4 o;
  o.x = fmaxf(a.x,0.f); o.y = fmaxf(a.y,0.f);
  o.z = fmaxf(a.z,0.f); o.w = fmaxf(a.w,0.f);
  ((float4*)(out + (rbase + r)*DD))[c4] = o;
}

// ---------------- launch ----------------
extern "C" void kernel_launch(void* const* d_in, const int* in_sizes, int n_in,
                              void* d_out, int out_size) {
  const float* x_seq   = (const float*)d_in[0];  // [4,32,256]
  const float* targets = (const float*)d_in[1];  // [4,32,256]
  const float* E       = (const float*)d_in[2];  // [256,1024]
  const float* Dy      = (const float*)d_in[3];  // [1024,256]
  float* out = (float*)d_out;                    // [4,32,256]

  int smem = (TT*NN + TT*COLS + NN + TT*COLS) * (int)sizeof(float);  // ~144 KB
  static int smem_set = 0;
  if (!smem_set) {
    cudaFuncSetAttribute(main_kernel, cudaFuncAttributeMaxDynamicSharedMemorySize, smem);
    smem_set = 1;
  }

  prep_kernel<<<BB*TT, 512>>>(x_seq, targets, E);   // also canary-fills g_p1/g_p2
  main_kernel<<<BB*GROUP, NTHR, smem>>>();
  out_kernel<<<32, 256>>>(Dy, out);
}